// round 2
// baseline (speedup 1.0000x reference)
#include <cuda_runtime.h>
#include <math.h>

#define SEQLEN   2048
#define HIDDEN   4096
#define NUM_HEADS 32
#define NUM_KV_HEADS 2
#define HEAD_DIM 128
#define QKV_OUT  ((NUM_HEADS + 2 * NUM_KV_HEADS) * HEAD_DIM)   // 4608
#define NQ       (NUM_HEADS * HEAD_DIM)                        // 4096
#define NKV      (NUM_KV_HEADS * HEAD_DIM)                     // 256
#define REP      (NUM_HEADS / NUM_KV_HEADS)                    // 16

// Scratch (device globals; no allocation allowed in kernel_launch)
__device__ float g_qkv[SEQLEN * QKV_OUT];    // ~37.7 MB
__device__ float g_attn[SEQLEN * NQ];        // ~33.5 MB

// ---------------------------------------------------------------------------
// GEMM: C[M,N] = A[M,K] @ B[K,N] (+ bias). 128x128 block tile, BK=8,
// 256 threads, 8x8 per thread in two 4-wide groups (cols tx*4 and 64+tx*4)
// to keep shared-memory bank conflicts low.
// ---------------------------------------------------------------------------
template <bool HAS_BIAS>
__global__ __launch_bounds__(256) void sgemm128(
    const float* __restrict__ A, const float* __restrict__ B,
    const float* __restrict__ bias, float* __restrict__ C,
    int M, int N, int K)
{
    __shared__ float As[8][128];
    __shared__ float Bs[8][128];

    const int tid  = threadIdx.x;
    const int brow = blockIdx.y * 128;
    const int bcol = blockIdx.x * 128;
    const int tx = tid & 15;   // 0..15
    const int ty = tid >> 4;   // 0..15

    const int a_row = tid >> 1;         // 0..127
    const int a_col = (tid & 1) * 4;    // 0 or 4
    const int b_row = tid >> 5;         // 0..7
    const int b_col = (tid & 31) * 4;   // 0..124

    const float* Ag = A + (size_t)(brow + a_row) * K + a_col;
    const float* Bg = B + (size_t)b_row * N + bcol + b_col;

    float acc[8][8];
    #pragma unroll
    for (int i = 0; i < 8; i++)
        #pragma unroll
        for (int j = 0; j < 8; j++) acc[i][j] = 0.0f;

    for (int k0 = 0; k0 < K; k0 += 8) {
        float4 av = *(const float4*)(Ag + k0);
        float4 bv = *(const float4*)(Bg + (size_t)k0 * N);
        As[a_col + 0][a_row] = av.x;
        As[a_col + 1][a_row] = av.y;
        As[a_col + 2][a_row] = av.z;
        As[a_col + 3][a_row] = av.w;
        *(float4*)&Bs[b_row][b_col] = bv;
        __syncthreads();

        #pragma unroll
        for (int kk = 0; kk < 8; kk++) {
            float ar[8], br[8];
            *(float4*)&ar[0] = *(const float4*)&As[kk][ty * 4];
            *(float4*)&ar[4] = *(const float4*)&As[kk][64 + ty * 4];
            *(float4*)&br[0] = *(const float4*)&Bs[kk][tx * 4];
            *(float4*)&br[4] = *(const float4*)&Bs[kk][64 + tx * 4];
            #pragma unroll
            for (int i = 0; i < 8; i++)
                #pragma unroll
                for (int j = 0; j < 8; j++)
                    acc[i][j] += ar[i] * br[j];
        }
        __syncthreads();
    }

    float bias0[4], bias1[4];
    if (HAS_BIAS) {
        #pragma unroll
        for (int j = 0; j < 4; j++) {
            bias0[j] = bias[bcol + tx * 4 + j];
            bias1[j] = bias[bcol + 64 + tx * 4 + j];
        }
    }

    #pragma unroll
    for (int i = 0; i < 8; i++) {
        int row = brow + ty * 4 + ((i < 4) ? i : 64 + (i - 4));
        float* crow = C + (size_t)row * N + bcol;
        float4 v0, v1;
        v0.x = acc[i][0]; v0.y = acc[i][1]; v0.z = acc[i][2]; v0.w = acc[i][3];
        v1.x = acc[i][4]; v1.y = acc[i][5]; v1.z = acc[i][6]; v1.w = acc[i][7];
        if (HAS_BIAS) {
            v0.x += bias0[0]; v0.y += bias0[1]; v0.z += bias0[2]; v0.w += bias0[3];
            v1.x += bias1[0]; v1.y += bias1[1]; v1.z += bias1[2]; v1.w += bias1[3];
        }
        *(float4*)(crow + tx * 4)      = v0;
        *(float4*)(crow + 64 + tx * 4) = v1;
    }
}

// ---------------------------------------------------------------------------
// RoPE (interleaved, rotary_dim=64) applied in-place to q (heads 0..31) and
// k (heads 32..33, contiguous right after q in the qkv row).
// ---------------------------------------------------------------------------
__global__ void rope_kernel(const float* __restrict__ cosb,
                            const float* __restrict__ sinb)
{
    int idx = blockIdx.x * blockDim.x + threadIdx.x;
    const int total = SEQLEN * (NUM_HEADS + NUM_KV_HEADS) * 32;
    if (idx >= total) return;
    int pair = idx & 31;
    int head = (idx >> 5) % (NUM_HEADS + NUM_KV_HEADS);
    int s    = idx / (32 * (NUM_HEADS + NUM_KV_HEADS));

    float c  = cosb[s * 64 + pair];   // cos[:, :32] used (repeat-2 interleave)
    float sn = sinb[s * 64 + pair];
    float* p = g_qkv + (size_t)s * QKV_OUT + head * HEAD_DIM + 2 * pair;
    float x0 = p[0], x1 = p[1];
    p[0] = x0 * c - x1 * sn;
    p[1] = x1 * c + x0 * sn;
}

// ---------------------------------------------------------------------------
// Flash attention (causal, GQA rep=16), fp32.
// Block = 256 threads handles BM=64 query rows for one head.
// Warp w, lane l: oct = l%8 owns dims [oct*16, oct*16+16);
// rows rl0 = w*8 + l/8 and rl0+4 (2 rows/thread for smem-load reuse).
// K/V tiles (BN=32 x 128) in smem with +4-per-16 skew -> conflict-free LDS.128.
// ---------------------------------------------------------------------------
#define BM 64
#define BN 32
#define KSTRIDE 160   // 128 + 8*4 skew floats

__global__ __launch_bounds__(256) void flash_kernel(float* __restrict__ out)
{
    __shared__ float Ks[BN][KSTRIDE];
    __shared__ float Vs[BN][KSTRIDE];

    const int tid  = threadIdx.x;
    const int warp = tid >> 5;
    const int lane = tid & 31;
    const int oct  = lane & 7;
    const int rl0  = warp * 8 + (lane >> 3);   // 0..63 (with +4 sibling)
    const int h    = blockIdx.y;
    const int kvh  = h / REP;
    const int q0   = blockIdx.x * BM;
    const int row0 = q0 + rl0;
    const int row1 = row0 + 4;
    const int octp = oct * 20;                  // physical smem col of oct*16

    float qf0[16], qf1[16];
    {
        const float* qp0 = g_qkv + (size_t)row0 * QKV_OUT + h * HEAD_DIM + oct * 16;
        const float* qp1 = g_qkv + (size_t)row1 * QKV_OUT + h * HEAD_DIM + oct * 16;
        #pragma unroll
        for (int i = 0; i < 16; i += 4) {
            float4 a = *(const float4*)(qp0 + i);
            qf0[i] = a.x; qf0[i+1] = a.y; qf0[i+2] = a.z; qf0[i+3] = a.w;
            float4 b = *(const float4*)(qp1 + i);
            qf1[i] = b.x; qf1[i+1] = b.y; qf1[i+2] = b.z; qf1[i+3] = b.w;
        }
    }

    float o0[16], o1[16];
    #pragma unroll
    for (int i = 0; i < 16; i++) { o0[i] = 0.0f; o1[i] = 0.0f; }
    float m0 = -1e30f, m1 = -1e30f, l0 = 0.0f, l1 = 0.0f;
    const float scale = 0.08838834764831845f;   // 1/sqrt(128)

    const int kend = q0 + BM;
    for (int j0 = 0; j0 < kend; j0 += BN) {
        __syncthreads();
        // cooperative K/V tile load (skewed layout)
        for (int t = tid; t < BN * 32; t += 256) {
            int r  = t >> 5;
            int c4 = (t & 31) * 4;
            int pc = c4 + ((c4 >> 4) << 2);
            const float* kp = g_qkv + (size_t)(j0 + r) * QKV_OUT + NQ + kvh * HEAD_DIM + c4;
            *(float4*)&Ks[r][pc] = *(const float4*)kp;
            *(float4*)&Vs[r][pc] = *(const float4*)(kp + NKV);
        }
        __syncthreads();

        float s0[BN], s1[BN];
        #pragma unroll
        for (int j = 0; j < BN; j++) {
            float p0 = 0.0f, p1 = 0.0f;
            #pragma unroll
            for (int i4 = 0; i4 < 16; i4 += 4) {
                float4 kv = *(const float4*)&Ks[j][octp + i4];
                p0 += qf0[i4] * kv.x + qf0[i4+1] * kv.y + qf0[i4+2] * kv.z + qf0[i4+3] * kv.w;
                p1 += qf1[i4] * kv.x + qf1[i4+1] * kv.y + qf1[i4+2] * kv.z + qf1[i4+3] * kv.w;
            }
            p0 += __shfl_xor_sync(0xffffffffu, p0, 1);
            p0 += __shfl_xor_sync(0xffffffffu, p0, 2);
            p0 += __shfl_xor_sync(0xffffffffu, p0, 4);
            p1 += __shfl_xor_sync(0xffffffffu, p1, 1);
            p1 += __shfl_xor_sync(0xffffffffu, p1, 2);
            p1 += __shfl_xor_sync(0xffffffffu, p1, 4);
            s0[j] = p0; s1[j] = p1;
        }

        float mt0 = m0, mt1 = m1;
        #pragma unroll
        for (int j = 0; j < BN; j++) {
            int key = j0 + j;
            s0[j] = (key <= row0) ? s0[j] * scale : -1e30f;
            s1[j] = (key <= row1) ? s1[j] * scale : -1e30f;
            mt0 = fmaxf(mt0, s0[j]);
            mt1 = fmaxf(mt1, s1[j]);
        }
        float c0 = __expf(m0 - mt0);
        float c1 = __expf(m1 - mt1);
        m0 = mt0; m1 = mt1;
        l0 *= c0;  l1 *= c1;
        #pragma unroll
        for (int i = 0; i < 16; i++) { o0[i] *= c0; o1[i] *= c1; }

        #pragma unroll
        for (int j = 0; j < BN; j++) {
            float p0 = __expf(s0[j] - m0);
            float p1 = __expf(s1[j] - m1);
            l0 += p0; l1 += p1;
            #pragma unroll
            for (int i4 = 0; i4 < 16; i4 += 4) {
                float4 vv = *(const float4*)&Vs[j][octp + i4];
                o0[i4]   += p0 * vv.x; o0[i4+1] += p0 * vv.y;
                o0[i4+2] += p0 * vv.z; o0[i4+3] += p0 * vv.w;
                o1[i4]   += p1 * vv.x; o1[i4+1] += p1 * vv.y;
                o1[i4+2] += p1 * vv.z; o1[i4+3] += p1 * vv.w;
            }
        }
    }

    float inv0 = 1.0f / l0;
    float inv1 = 1.0f / l1;
    float* op0 = out + (size_t)row0 * NQ + h * HEAD_DIM + oct * 16;
    float* op1 = out + (size_t)row1 * NQ + h * HEAD_DIM + oct * 16;
    #pragma unroll
    for (int i = 0; i < 16; i += 4) {
        float4 a; a.x = o0[i]*inv0; a.y = o0[i+1]*inv0; a.z = o0[i+2]*inv0; a.w = o0[i+3]*inv0;
        float4 b; b.x = o1[i]*inv1; b.y = o1[i+1]*inv1; b.z = o1[i+2]*inv1; b.w = o1[i+3]*inv1;
        *(float4*)(op0 + i) = a;
        *(float4*)(op1 + i) = b;
    }
}

// ---------------------------------------------------------------------------
// Launch
// ---------------------------------------------------------------------------
extern "C" void kernel_launch(void* const* d_in, const int* in_sizes, int n_in,
                              void* d_out, int out_size)
{
    const float* hidden = (const float*)d_in[0];
    const float* cosb   = (const float*)d_in[1];
    const float* sinb   = (const float*)d_in[2];
    const float* w_qkv  = (const float*)d_in[3];
    const float* b_qkv  = (const float*)d_in[4];
    const float* w_o    = (const float*)d_in[5];
    float* out = (float*)d_out;

    float* qkv = nullptr;
    float* attn = nullptr;
    cudaGetSymbolAddress((void**)&qkv, g_qkv);
    cudaGetSymbolAddress((void**)&attn, g_attn);

    // 1) QKV projection + bias
    sgemm128<true><<<dim3(QKV_OUT / 128, SEQLEN / 128), 256>>>(
        hidden, w_qkv, b_qkv, qkv, SEQLEN, QKV_OUT, HIDDEN);

    // 2) RoPE in-place on q + k
    {
        int total = SEQLEN * (NUM_HEADS + NUM_KV_HEADS) * 32;
        rope_kernel<<<(total + 255) / 256, 256>>>(cosb, sinb);
    }

    // 3) causal GQA flash attention
    flash_kernel<<<dim3(SEQLEN / BM, NUM_HEADS), 256>>>(attn);

    // 4) output projection
    sgemm128<false><<<dim3(HIDDEN / 128, SEQLEN / 128), 256>>>(
        attn, w_o, nullptr, out, SEQLEN, HIDDEN, NQ);
}

// round 4
// speedup vs baseline: 1.8019x; 1.8019x over previous
#include <cuda_runtime.h>
#include <cstdint>
#include <math.h>

#define SEQLEN   2048
#define HIDDEN   4096
#define NUM_HEADS 32
#define NUM_KV_HEADS 2
#define HEAD_DIM 128
#define QKV_OUT  ((NUM_HEADS + 2 * NUM_KV_HEADS) * HEAD_DIM)   // 4608
#define NQ       (NUM_HEADS * HEAD_DIM)                        // 4096
#define NKV      (NUM_KV_HEADS * HEAD_DIM)                     // 256
#define REP      (NUM_HEADS / NUM_KV_HEADS)                    // 16

// Scratch (device globals; no allocation allowed in kernel_launch)
__device__ float g_qkv[SEQLEN * QKV_OUT];        // ~37.7 MB
__device__ float g_attn[SEQLEN * NQ];            // ~33.5 MB
__device__ float g_Ar[SEQLEN * HIDDEN];          // 32 MB  (tf32-rounded A)
__device__ float g_Br[HIDDEN * QKV_OUT];         // 72 MB  (tf32-rounded B)

// ===========================================================================
// helpers
// ===========================================================================
__device__ __forceinline__ float tf32_round(float f) {
    uint32_t u;
    asm("cvt.rna.tf32.f32 %0, %1;" : "=r"(u) : "f"(f));
    return __uint_as_float(u);
}
__device__ __forceinline__ uint32_t smem_u32(const void* p) {
    uint32_t a;
    asm("{ .reg .u64 t; cvta.to.shared.u64 t, %1; cvt.u32.u64 %0, t; }"
        : "=r"(a) : "l"(p));
    return a;
}
__device__ __forceinline__ void cp_async16(uint32_t dst, const void* src) {
    asm volatile("cp.async.cg.shared.global [%0], [%1], 16;" :: "r"(dst), "l"(src));
}
#define CP_COMMIT() asm volatile("cp.async.commit_group;" ::: "memory")
#define CP_WAIT1()  asm volatile("cp.async.wait_group 1;" ::: "memory")

__device__ __forceinline__ void mma_tf32(float* c, const uint32_t* a, const uint32_t* b) {
    asm volatile(
        "mma.sync.aligned.m16n8k8.row.col.f32.tf32.tf32.f32 "
        "{%0,%1,%2,%3}, {%4,%5,%6,%7}, {%8,%9}, {%0,%1,%2,%3};"
        : "+f"(c[0]), "+f"(c[1]), "+f"(c[2]), "+f"(c[3])
        : "r"(a[0]), "r"(a[1]), "r"(a[2]), "r"(a[3]), "r"(b[0]), "r"(b[1]));
}

// ===========================================================================
// elementwise tf32 rounding pass (float4 vectorized; sizes are /4)
// ===========================================================================
__global__ void round_tf32_kernel(const float* __restrict__ in,
                                  float* __restrict__ out, int n4)
{
    int i = blockIdx.x * blockDim.x + threadIdx.x;
    if (i >= n4) return;
    float4 v = ((const float4*)in)[i];
    v.x = tf32_round(v.x); v.y = tf32_round(v.y);
    v.z = tf32_round(v.z); v.w = tf32_round(v.w);
    ((float4*)out)[i] = v;
}

// ===========================================================================
// tf32 mma.sync GEMM: C[M,N] = A[M,K] @ B[K,N] (+bias)
// CTA tile 128x128x32, 8 warps (2 x 4), warp tile 64x32, 3-stage cp.async.
// A smem [128][36] row-major (stride 36 fl), B smem [32][136] (stride 136 fl).
// Inputs must already be tf32-rounded (mantissa low bits zero).
// ===========================================================================
#define ASTR 36
#define BSTR 136
#define A_FL (128 * ASTR)                 // 4608 floats
#define B_FL (32 * BSTR)                  // 4352 floats
#define STAGE_FL (A_FL + B_FL)            // 8960 floats
#define GSMEM_BYTES (3 * STAGE_FL * 4)    // 107520 bytes

template <bool HAS_BIAS>
__global__ __launch_bounds__(256)
void gemm_mma(const float* __restrict__ A, const float* __restrict__ B,
              const float* __restrict__ bias, float* __restrict__ C,
              int K, int ldb, int N)
{
    extern __shared__ float smem[];
    const uint32_t sbase = smem_u32(smem);

    const int tid  = threadIdx.x;
    const int warp = tid >> 5;
    const int lane = tid & 31;
    const int g    = lane >> 2;        // group id (row within fragment)
    const int t    = lane & 3;         // thread in group (col/k within fragment)
    const int wm   = warp & 1;         // 0..1  -> 64-row slab
    const int wn   = warp >> 1;        // 0..3  -> 32-col slab
    const int brow = blockIdx.y * 128;
    const int n0   = blockIdx.x * 128;

    // ---- pipelined loads -------------------------------------------------
    auto load_stage = [&](int s, int k0) {
        const float* Ap = A + (size_t)brow * K + k0;
        const float* Bp = B + (size_t)k0 * ldb + n0;
        const uint32_t sA = sbase + (uint32_t)s * (STAGE_FL * 4);
        const uint32_t sB = sA + A_FL * 4;
        #pragma unroll
        for (int p = 0; p < 4; p++) {
            int id = tid + p * 256;
            int r = id >> 3, c = (id & 7) << 2;
            cp_async16(sA + (uint32_t)(r * ASTR + c) * 4, Ap + (size_t)r * K + c);
        }
        #pragma unroll
        for (int p = 0; p < 4; p++) {
            int id = tid + p * 256;
            int r = id >> 5, c = (id & 31) << 2;
            cp_async16(sB + (uint32_t)(r * BSTR + c) * 4, Bp + (size_t)r * ldb + c);
        }
    };

    const int iters = K / 32;
    load_stage(0, 0);  CP_COMMIT();
    load_stage(1, 32); CP_COMMIT();

    float acc[4][4][4];
    #pragma unroll
    for (int mt = 0; mt < 4; mt++)
        #pragma unroll
        for (int nt = 0; nt < 4; nt++)
            #pragma unroll
            for (int q = 0; q < 4; q++) acc[mt][nt][q] = 0.0f;

    for (int i = 0; i < iters; i++) {
        CP_WAIT1();
        __syncthreads();

        const float* As = smem + (i % 3) * STAGE_FL;
        const float* Bs = As + A_FL;

        #pragma unroll
        for (int kk = 0; kk < 4; kk++) {
            const int k = kk * 8;
            uint32_t a[4][4];
            #pragma unroll
            for (int mt = 0; mt < 4; mt++) {
                const float* ap = As + (wm * 64 + mt * 16 + g) * ASTR + k + t;
                a[mt][0] = __float_as_uint(ap[0]);
                a[mt][1] = __float_as_uint(ap[8 * ASTR]);
                a[mt][2] = __float_as_uint(ap[4]);
                a[mt][3] = __float_as_uint(ap[8 * ASTR + 4]);
            }
            uint32_t b[4][2];
            #pragma unroll
            for (int nt = 0; nt < 4; nt++) {
                const float* bp = Bs + (k + t) * BSTR + wn * 32 + nt * 8 + g;
                b[nt][0] = __float_as_uint(bp[0]);
                b[nt][1] = __float_as_uint(bp[4 * BSTR]);
            }
            #pragma unroll
            for (int mt = 0; mt < 4; mt++)
                #pragma unroll
                for (int nt = 0; nt < 4; nt++)
                    mma_tf32(acc[mt][nt], a[mt], b[nt]);
        }

        __syncthreads();
        if (i + 2 < iters) load_stage((i + 2) % 3, (i + 2) * 32);
        CP_COMMIT();
    }

    // ---- epilogue --------------------------------------------------------
    #pragma unroll
    for (int mt = 0; mt < 4; mt++) {
        #pragma unroll
        for (int nt = 0; nt < 4; nt++) {
            const int row = brow + wm * 64 + mt * 16 + g;
            const int col = n0 + wn * 32 + nt * 8 + 2 * t;
            float bx = 0.f, by = 0.f;
            if (HAS_BIAS) { bx = bias[col]; by = bias[col + 1]; }
            float2 v0 = make_float2(acc[mt][nt][0] + bx, acc[mt][nt][1] + by);
            float2 v1 = make_float2(acc[mt][nt][2] + bx, acc[mt][nt][3] + by);
            *(float2*)&C[(size_t)row * N + col]       = v0;
            *(float2*)&C[(size_t)(row + 8) * N + col] = v1;
        }
    }
}

// ---------------------------------------------------------------------------
// RoPE (interleaved, rotary_dim=64) in-place on q (heads 0..31) and k.
// ---------------------------------------------------------------------------
__global__ void rope_kernel(const float* __restrict__ cosb,
                            const float* __restrict__ sinb)
{
    int idx = blockIdx.x * blockDim.x + threadIdx.x;
    const int total = SEQLEN * (NUM_HEADS + NUM_KV_HEADS) * 32;
    if (idx >= total) return;
    int pair = idx & 31;
    int head = (idx >> 5) % (NUM_HEADS + NUM_KV_HEADS);
    int s    = idx / (32 * (NUM_HEADS + NUM_KV_HEADS));

    float c  = cosb[s * 64 + pair];
    float sn = sinb[s * 64 + pair];
    float* p = g_qkv + (size_t)s * QKV_OUT + head * HEAD_DIM + 2 * pair;
    float x0 = p[0], x1 = p[1];
    p[0] = x0 * c - x1 * sn;
    p[1] = x1 * c + x0 * sn;
}

// ---------------------------------------------------------------------------
// Flash attention (causal, GQA rep=16), fp32. Output tf32-rounded for GEMM2.
// ---------------------------------------------------------------------------
#define BM 64
#define BN 32
#define KSTRIDE 160

__global__ __launch_bounds__(256) void flash_kernel(float* __restrict__ out)
{
    __shared__ float Ks[BN][KSTRIDE];
    __shared__ float Vs[BN][KSTRIDE];

    const int tid  = threadIdx.x;
    const int warp = tid >> 5;
    const int lane = tid & 31;
    const int oct  = lane & 7;
    const int rl0  = warp * 8 + (lane >> 3);
    const int h    = blockIdx.y;
    const int kvh  = h / REP;
    const int q0   = blockIdx.x * BM;
    const int row0 = q0 + rl0;
    const int row1 = row0 + 4;
    const int octp = oct * 20;

    float qf0[16], qf1[16];
    {
        const float* qp0 = g_qkv + (size_t)row0 * QKV_OUT + h * HEAD_DIM + oct * 16;
        const float* qp1 = g_qkv + (size_t)row1 * QKV_OUT + h * HEAD_DIM + oct * 16;
        #pragma unroll
        for (int i = 0; i < 16; i += 4) {
            float4 a = *(const float4*)(qp0 + i);
            qf0[i] = a.x; qf0[i+1] = a.y; qf0[i+2] = a.z; qf0[i+3] = a.w;
            float4 b = *(const float4*)(qp1 + i);
            qf1[i] = b.x; qf1[i+1] = b.y; qf1[i+2] = b.z; qf1[i+3] = b.w;
        }
    }

    float o0[16], o1[16];
    #pragma unroll
    for (int i = 0; i < 16; i++) { o0[i] = 0.0f; o1[i] = 0.0f; }
    float m0 = -1e30f, m1 = -1e30f, l0 = 0.0f, l1 = 0.0f;
    const float scale = 0.08838834764831845f;

    const int kend = q0 + BM;
    for (int j0 = 0; j0 < kend; j0 += BN) {
        __syncthreads();
        for (int t = tid; t < BN * 32; t += 256) {
            int r  = t >> 5;
            int c4 = (t & 31) * 4;
            int pc = c4 + ((c4 >> 4) << 2);
            const float* kp = g_qkv + (size_t)(j0 + r) * QKV_OUT + NQ + kvh * HEAD_DIM + c4;
            *(float4*)&Ks[r][pc] = *(const float4*)kp;
            *(float4*)&Vs[r][pc] = *(const float4*)(kp + NKV);
        }
        __syncthreads();

        float s0[BN], s1[BN];
        #pragma unroll
        for (int j = 0; j < BN; j++) {
            float p0 = 0.0f, p1 = 0.0f;
            #pragma unroll
            for (int i4 = 0; i4 < 16; i4 += 4) {
                float4 kv = *(const float4*)&Ks[j][octp + i4];
                p0 += qf0[i4] * kv.x + qf0[i4+1] * kv.y + qf0[i4+2] * kv.z + qf0[i4+3] * kv.w;
                p1 += qf1[i4] * kv.x + qf1[i4+1] * kv.y + qf1[i4+2] * kv.z + qf1[i4+3] * kv.w;
            }
            p0 += __shfl_xor_sync(0xffffffffu, p0, 1);
            p0 += __shfl_xor_sync(0xffffffffu, p0, 2);
            p0 += __shfl_xor_sync(0xffffffffu, p0, 4);
            p1 += __shfl_xor_sync(0xffffffffu, p1, 1);
            p1 += __shfl_xor_sync(0xffffffffu, p1, 2);
            p1 += __shfl_xor_sync(0xffffffffu, p1, 4);
            s0[j] = p0; s1[j] = p1;
        }

        float mt0 = m0, mt1 = m1;
        #pragma unroll
        for (int j = 0; j < BN; j++) {
            int key = j0 + j;
            s0[j] = (key <= row0) ? s0[j] * scale : -1e30f;
            s1[j] = (key <= row1) ? s1[j] * scale : -1e30f;
            mt0 = fmaxf(mt0, s0[j]);
            mt1 = fmaxf(mt1, s1[j]);
        }
        float c0 = __expf(m0 - mt0);
        float c1 = __expf(m1 - mt1);
        m0 = mt0; m1 = mt1;
        l0 *= c0;  l1 *= c1;
        #pragma unroll
        for (int i = 0; i < 16; i++) { o0[i] *= c0; o1[i] *= c1; }

        #pragma unroll
        for (int j = 0; j < BN; j++) {
            float p0 = __expf(s0[j] - m0);
            float p1 = __expf(s1[j] - m1);
            l0 += p0; l1 += p1;
            #pragma unroll
            for (int i4 = 0; i4 < 16; i4 += 4) {
                float4 vv = *(const float4*)&Vs[j][octp + i4];
                o0[i4]   += p0 * vv.x; o0[i4+1] += p0 * vv.y;
                o0[i4+2] += p0 * vv.z; o0[i4+3] += p0 * vv.w;
                o1[i4]   += p1 * vv.x; o1[i4+1] += p1 * vv.y;
                o1[i4+2] += p1 * vv.z; o1[i4+3] += p1 * vv.w;
            }
        }
    }

    float inv0 = 1.0f / l0;
    float inv1 = 1.0f / l1;
    float* op0 = out + (size_t)row0 * NQ + h * HEAD_DIM + oct * 16;
    float* op1 = out + (size_t)row1 * NQ + h * HEAD_DIM + oct * 16;
    #pragma unroll
    for (int i = 0; i < 16; i += 4) {
        float4 a;
        a.x = tf32_round(o0[i]   * inv0); a.y = tf32_round(o0[i+1] * inv0);
        a.z = tf32_round(o0[i+2] * inv0); a.w = tf32_round(o0[i+3] * inv0);
        float4 b;
        b.x = tf32_round(o1[i]   * inv1); b.y = tf32_round(o1[i+1] * inv1);
        b.z = tf32_round(o1[i+2] * inv1); b.w = tf32_round(o1[i+3] * inv1);
        *(float4*)(op0 + i) = a;
        *(float4*)(op1 + i) = b;
    }
}

// ---------------------------------------------------------------------------
// Launch
// ---------------------------------------------------------------------------
extern "C" void kernel_launch(void* const* d_in, const int* in_sizes, int n_in,
                              void* d_out, int out_size)
{
    const float* hidden = (const float*)d_in[0];
    const float* cosb   = (const float*)d_in[1];
    const float* sinb   = (const float*)d_in[2];
    const float* w_qkv  = (const float*)d_in[3];
    const float* b_qkv  = (const float*)d_in[4];
    const float* w_o    = (const float*)d_in[5];
    float* out = (float*)d_out;

    float *qkv = nullptr, *attn = nullptr, *Ar = nullptr, *Br = nullptr;
    cudaGetSymbolAddress((void**)&qkv,  g_qkv);
    cudaGetSymbolAddress((void**)&attn, g_attn);
    cudaGetSymbolAddress((void**)&Ar,   g_Ar);
    cudaGetSymbolAddress((void**)&Br,   g_Br);

    cudaFuncSetAttribute(gemm_mma<true>,  cudaFuncAttributeMaxDynamicSharedMemorySize, GSMEM_BYTES);
    cudaFuncSetAttribute(gemm_mma<false>, cudaFuncAttributeMaxDynamicSharedMemorySize, GSMEM_BYTES);

    // 0) tf32-round GEMM1 operands
    {
        int n4 = SEQLEN * HIDDEN / 4;
        round_tf32_kernel<<<(n4 + 255) / 256, 256>>>(hidden, Ar, n4);
        n4 = HIDDEN * QKV_OUT / 4;
        round_tf32_kernel<<<(n4 + 255) / 256, 256>>>(w_qkv, Br, n4);
    }

    // 1) QKV projection + bias (tf32 mma.sync)
    gemm_mma<true><<<dim3(QKV_OUT / 128, SEQLEN / 128), 256, GSMEM_BYTES>>>(
        Ar, Br, b_qkv, qkv, HIDDEN, QKV_OUT, QKV_OUT);

    // 2) RoPE in-place on q + k
    {
        int total = SEQLEN * (NUM_HEADS + NUM_KV_HEADS) * 32;
        rope_kernel<<<(total + 255) / 256, 256>>>(cosb, sinb);
    }

    // 3) causal GQA flash attention (fp32, tf32-rounded output)
    flash_kernel<<<dim3(SEQLEN / BM, NUM_HEADS), 256>>>(attn);

    // 4) tf32-round w_o (stream-ordered after GEMM1: safe to reuse Br)
    {
        int n4 = NQ * HIDDEN / 4;
        round_tf32_kernel<<<(n4 + 255) / 256, 256>>>(w_o, Br, n4);
    }

    // 5) output projection (tf32 mma.sync)
    gemm_mma<false><<<dim3(HIDDEN / 128, SEQLEN / 128), 256, GSMEM_BYTES>>>(
        attn, Br, nullptr, out, NQ, HIDDEN, HIDDEN);
}

// round 5
// speedup vs baseline: 3.5647x; 1.9783x over previous
#include <cuda_runtime.h>
#include <cstdint>
#include <math.h>

#define SEQLEN   2048
#define HIDDEN   4096
#define NUM_HEADS 32
#define NUM_KV_HEADS 2
#define HEAD_DIM 128
#define QKV_OUT  ((NUM_HEADS + 2 * NUM_KV_HEADS) * HEAD_DIM)   // 4608
#define NQ       (NUM_HEADS * HEAD_DIM)                        // 4096
#define NKV      (NUM_KV_HEADS * HEAD_DIM)                     // 256
#define REP      (NUM_HEADS / NUM_KV_HEADS)                    // 16

// Scratch (device globals; no allocation allowed in kernel_launch)
__device__ float g_qkv[SEQLEN * QKV_OUT];        // ~37.7 MB
__device__ float g_attn[SEQLEN * NQ];            // ~33.5 MB
__device__ float g_Ar[SEQLEN * HIDDEN];          // 32 MB  (tf32-rounded A)
__device__ float g_Br[HIDDEN * QKV_OUT];         // 72 MB  (tf32-rounded B)

// ===========================================================================
// helpers
// ===========================================================================
__device__ __forceinline__ float tf32_round(float f) {
    uint32_t u;
    asm("cvt.rna.tf32.f32 %0, %1;" : "=r"(u) : "f"(f));
    return __uint_as_float(u);
}
__device__ __forceinline__ uint32_t smem_u32(const void* p) {
    uint32_t a;
    asm("{ .reg .u64 t; cvta.to.shared.u64 t, %1; cvt.u32.u64 %0, t; }"
        : "=r"(a) : "l"(p));
    return a;
}
__device__ __forceinline__ void cp_async16(uint32_t dst, const void* src) {
    asm volatile("cp.async.cg.shared.global [%0], [%1], 16;" :: "r"(dst), "l"(src));
}
#define CP_COMMIT() asm volatile("cp.async.commit_group;" ::: "memory")
#define CP_WAIT1()  asm volatile("cp.async.wait_group 1;" ::: "memory")

__device__ __forceinline__ void mma_tf32(float* c, const uint32_t* a, const uint32_t* b) {
    asm volatile(
        "mma.sync.aligned.m16n8k8.row.col.f32.tf32.tf32.f32 "
        "{%0,%1,%2,%3}, {%4,%5,%6,%7}, {%8,%9}, {%0,%1,%2,%3};"
        : "+f"(c[0]), "+f"(c[1]), "+f"(c[2]), "+f"(c[3])
        : "r"(a[0]), "r"(a[1]), "r"(a[2]), "r"(a[3]), "r"(b[0]), "r"(b[1]));
}

// ===========================================================================
// elementwise tf32 rounding pass (float4 vectorized; in-place allowed)
// ===========================================================================
__global__ void round_tf32_kernel(const float* __restrict__ in,
                                  float* __restrict__ out, int n4)
{
    int i = blockIdx.x * blockDim.x + threadIdx.x;
    if (i >= n4) return;
    float4 v = ((const float4*)in)[i];
    v.x = tf32_round(v.x); v.y = tf32_round(v.y);
    v.z = tf32_round(v.z); v.w = tf32_round(v.w);
    ((float4*)out)[i] = v;
}

// ===========================================================================
// tf32 mma.sync GEMM: C[M,N] = A[M,K] @ B[K,N] (+bias)   (unchanged from R4)
// ===========================================================================
#define ASTR 36
#define BSTR 136
#define A_FL (128 * ASTR)
#define B_FL (32 * BSTR)
#define STAGE_FL (A_FL + B_FL)
#define GSMEM_BYTES (3 * STAGE_FL * 4)

template <bool HAS_BIAS>
__global__ __launch_bounds__(256)
void gemm_mma(const float* __restrict__ A, const float* __restrict__ B,
              const float* __restrict__ bias, float* __restrict__ C,
              int K, int ldb, int N)
{
    extern __shared__ float smem[];
    const uint32_t sbase = smem_u32(smem);

    const int tid  = threadIdx.x;
    const int warp = tid >> 5;
    const int lane = tid & 31;
    const int g    = lane >> 2;
    const int t    = lane & 3;
    const int wm   = warp & 1;
    const int wn   = warp >> 1;
    const int brow = blockIdx.y * 128;
    const int n0   = blockIdx.x * 128;

    auto load_stage = [&](int s, int k0) {
        const float* Ap = A + (size_t)brow * K + k0;
        const float* Bp = B + (size_t)k0 * ldb + n0;
        const uint32_t sA = sbase + (uint32_t)s * (STAGE_FL * 4);
        const uint32_t sB = sA + A_FL * 4;
        #pragma unroll
        for (int p = 0; p < 4; p++) {
            int id = tid + p * 256;
            int r = id >> 3, c = (id & 7) << 2;
            cp_async16(sA + (uint32_t)(r * ASTR + c) * 4, Ap + (size_t)r * K + c);
        }
        #pragma unroll
        for (int p = 0; p < 4; p++) {
            int id = tid + p * 256;
            int r = id >> 5, c = (id & 31) << 2;
            cp_async16(sB + (uint32_t)(r * BSTR + c) * 4, Bp + (size_t)r * ldb + c);
        }
    };

    const int iters = K / 32;
    load_stage(0, 0);  CP_COMMIT();
    load_stage(1, 32); CP_COMMIT();

    float acc[4][4][4];
    #pragma unroll
    for (int mt = 0; mt < 4; mt++)
        #pragma unroll
        for (int nt = 0; nt < 4; nt++)
            #pragma unroll
            for (int q = 0; q < 4; q++) acc[mt][nt][q] = 0.0f;

    for (int i = 0; i < iters; i++) {
        CP_WAIT1();
        __syncthreads();

        const float* As = smem + (i % 3) * STAGE_FL;
        const float* Bs = As + A_FL;

        #pragma unroll
        for (int kk = 0; kk < 4; kk++) {
            const int k = kk * 8;
            uint32_t a[4][4];
            #pragma unroll
            for (int mt = 0; mt < 4; mt++) {
                const float* ap = As + (wm * 64 + mt * 16 + g) * ASTR + k + t;
                a[mt][0] = __float_as_uint(ap[0]);
                a[mt][1] = __float_as_uint(ap[8 * ASTR]);
                a[mt][2] = __float_as_uint(ap[4]);
                a[mt][3] = __float_as_uint(ap[8 * ASTR + 4]);
            }
            uint32_t b[4][2];
            #pragma unroll
            for (int nt = 0; nt < 4; nt++) {
                const float* bp = Bs + (k + t) * BSTR + wn * 32 + nt * 8 + g;
                b[nt][0] = __float_as_uint(bp[0]);
                b[nt][1] = __float_as_uint(bp[4 * BSTR]);
            }
            #pragma unroll
            for (int mt = 0; mt < 4; mt++)
                #pragma unroll
                for (int nt = 0; nt < 4; nt++)
                    mma_tf32(acc[mt][nt], a[mt], b[nt]);
        }

        __syncthreads();
        if (i + 2 < iters) load_stage((i + 2) % 3, (i + 2) * 32);
        CP_COMMIT();
    }

    #pragma unroll
    for (int mt = 0; mt < 4; mt++) {
        #pragma unroll
        for (int nt = 0; nt < 4; nt++) {
            const int row = brow + wm * 64 + mt * 16 + g;
            const int col = n0 + wn * 32 + nt * 8 + 2 * t;
            float bx = 0.f, by = 0.f;
            if (HAS_BIAS) { bx = bias[col]; by = bias[col + 1]; }
            float2 v0 = make_float2(acc[mt][nt][0] + bx, acc[mt][nt][1] + by);
            float2 v1 = make_float2(acc[mt][nt][2] + bx, acc[mt][nt][3] + by);
            *(float2*)&C[(size_t)row * N + col]       = v0;
            *(float2*)&C[(size_t)(row + 8) * N + col] = v1;
        }
    }
}

// ---------------------------------------------------------------------------
// RoPE (interleaved, rotary_dim=64) in-place on q (heads 0..31) and k.
// ---------------------------------------------------------------------------
__global__ void rope_kernel(const float* __restrict__ cosb,
                            const float* __restrict__ sinb)
{
    int idx = blockIdx.x * blockDim.x + threadIdx.x;
    const int total = SEQLEN * (NUM_HEADS + NUM_KV_HEADS) * 32;
    if (idx >= total) return;
    int pair = idx & 31;
    int head = (idx >> 5) % (NUM_HEADS + NUM_KV_HEADS);
    int s    = idx / (32 * (NUM_HEADS + NUM_KV_HEADS));

    float c  = cosb[s * 64 + pair];
    float sn = sinb[s * 64 + pair];
    float* p = g_qkv + (size_t)s * QKV_OUT + head * HEAD_DIM + 2 * pair;
    float x0 = p[0], x1 = p[1];
    p[0] = x0 * c - x1 * sn;
    p[1] = x1 * c + x0 * sn;
}

// ===========================================================================
// Flash attention (causal, GQA rep=16) on tensor cores (tf32 mma.sync).
// BM=128 q rows (8 warps x 16), BN=64 keys/iter, K/V double-buffered cp.async.
// g_qkv must already be tf32-rounded (K and V read raw as mma operands).
// ===========================================================================
#define FBM 128
#define FBN 64
#define KSTR 132            // 132 mod 32 = 4  -> QK B-frag LDS conflict-free
#define VSTR 136            // 136 mod 32 = 8  -> PV B-frag LDS conflict-free
#define FSTAGE_FL (FBN * KSTR + FBN * VSTR)     // 17152 floats
#define FSMEM_BYTES (2 * FSTAGE_FL * 4)         // 137216 bytes

__global__ __launch_bounds__(256, 1) void flash_tc(float* __restrict__ out)
{
    extern __shared__ float fs[];
    const uint32_t sbase = smem_u32(fs);

    const int tid  = threadIdx.x;
    const int warp = tid >> 5;
    const int lane = tid & 31;
    const int g    = lane >> 2;
    const int t    = lane & 3;
    const int h    = blockIdx.y;
    const int kvh  = h / REP;
    const int q0   = blockIdx.x * FBM;
    const int r0   = q0 + warp * 16 + g;      // fragment row g
    const int r1   = r0 + 8;                  // fragment row g+8
    const float scale = 0.08838834764831845f; // 1/sqrt(128)

    // ---- Q fragments, pre-scaled + tf32-rounded, resident in registers ----
    uint32_t qa[16][4];
    {
        const float* qb = g_qkv + (size_t)(q0 + warp * 16) * QKV_OUT + h * HEAD_DIM;
        #pragma unroll
        for (int ks = 0; ks < 16; ks++) {
            qa[ks][0] = __float_as_uint(tf32_round(qb[(size_t)g       * QKV_OUT + ks * 8 + t]     * scale));
            qa[ks][1] = __float_as_uint(tf32_round(qb[(size_t)(g + 8) * QKV_OUT + ks * 8 + t]     * scale));
            qa[ks][2] = __float_as_uint(tf32_round(qb[(size_t)g       * QKV_OUT + ks * 8 + t + 4] * scale));
            qa[ks][3] = __float_as_uint(tf32_round(qb[(size_t)(g + 8) * QKV_OUT + ks * 8 + t + 4] * scale));
        }
    }

    // ---- K/V tile loader (stage s in {0,1}) ----
    auto load_kv = [&](int s, int kb) {
        const uint32_t sK = sbase + (uint32_t)s * (FSTAGE_FL * 4);
        const uint32_t sV = sK + FBN * KSTR * 4;
        const float* src = g_qkv + (size_t)(kb * FBN) * QKV_OUT + NQ + kvh * HEAD_DIM;
        #pragma unroll
        for (int p = 0; p < 8; p++) {
            int id = tid + p * 256;
            int r = id >> 5;             // 0..63
            int c = (id & 31) << 2;      // 0..124
            const float* rp = src + (size_t)r * QKV_OUT + c;
            cp_async16(sK + (uint32_t)(r * KSTR + c) * 4, rp);
            cp_async16(sV + (uint32_t)(r * VSTR + c) * 4, rp + NKV);
        }
    };

    float o[16][4];
    #pragma unroll
    for (int d = 0; d < 16; d++)
        #pragma unroll
        for (int q = 0; q < 4; q++) o[d][q] = 0.0f;
    float m0 = -1e30f, m1 = -1e30f, l0 = 0.0f, l1 = 0.0f;

    const int nkb = (q0 + FBM) / FBN;    // >= 2 always
    load_kv(0, 0); CP_COMMIT();
    load_kv(1, 1); CP_COMMIT();

    const int srcA = (lane & ~3) | (t >> 1);   // quad-internal shfl sources
    const int srcB = srcA + 2;
    const int selo = t & 1;

    for (int kb = 0; kb < nkb; kb++) {
        CP_WAIT1();
        __syncthreads();
        const float* Ks = fs + (kb & 1) * FSTAGE_FL;
        const float* Vs = Ks + FBN * KSTR;

        // ---- S = Q K^T (scaled) ----
        float sc[8][4];
        #pragma unroll
        for (int j = 0; j < 8; j++)
            #pragma unroll
            for (int q = 0; q < 4; q++) sc[j][q] = 0.0f;

        #pragma unroll
        for (int ks = 0; ks < 16; ks++) {
            const int kd = ks * 8;
            #pragma unroll
            for (int j = 0; j < 8; j++) {
                uint32_t b[2];
                const float* kp = Ks + (j * 8 + g) * KSTR + kd + t;
                b[0] = __float_as_uint(kp[0]);
                b[1] = __float_as_uint(kp[4]);
                mma_tf32(sc[j], qa[ks], b);
            }
        }

        // ---- causal mask (only needed on the last two k-blocks) ----
        if (kb >= nkb - 2) {
            const int keyb = kb * FBN + 2 * t;
            #pragma unroll
            for (int j = 0; j < 8; j++) {
                int k0 = keyb + j * 8;
                if (k0     > r0) sc[j][0] = -1e30f;
                if (k0 + 1 > r0) sc[j][1] = -1e30f;
                if (k0     > r1) sc[j][2] = -1e30f;
                if (k0 + 1 > r1) sc[j][3] = -1e30f;
            }
        }

        // ---- online softmax ----
        float mx0 = -1e30f, mx1 = -1e30f;
        #pragma unroll
        for (int j = 0; j < 8; j++) {
            mx0 = fmaxf(mx0, fmaxf(sc[j][0], sc[j][1]));
            mx1 = fmaxf(mx1, fmaxf(sc[j][2], sc[j][3]));
        }
        mx0 = fmaxf(mx0, __shfl_xor_sync(0xffffffffu, mx0, 1));
        mx0 = fmaxf(mx0, __shfl_xor_sync(0xffffffffu, mx0, 2));
        mx1 = fmaxf(mx1, __shfl_xor_sync(0xffffffffu, mx1, 1));
        mx1 = fmaxf(mx1, __shfl_xor_sync(0xffffffffu, mx1, 2));
        const float mn0 = fmaxf(m0, mx0);
        const float mn1 = fmaxf(m1, mx1);
        const float c0 = __expf(m0 - mn0);
        const float c1 = __expf(m1 - mn1);
        m0 = mn0; m1 = mn1;
        l0 *= c0;  l1 *= c1;
        #pragma unroll
        for (int d = 0; d < 16; d++) {
            o[d][0] *= c0; o[d][1] *= c0;
            o[d][2] *= c1; o[d][3] *= c1;
        }

        uint32_t pc[8][4];
        #pragma unroll
        for (int j = 0; j < 8; j++) {
            float p0 = __expf(sc[j][0] - m0);
            float p1 = __expf(sc[j][1] - m0);
            float p2 = __expf(sc[j][2] - m1);
            float p3 = __expf(sc[j][3] - m1);
            l0 += p0 + p1;
            l1 += p2 + p3;
            pc[j][0] = __float_as_uint(tf32_round(p0));
            pc[j][1] = __float_as_uint(tf32_round(p1));
            pc[j][2] = __float_as_uint(tf32_round(p2));
            pc[j][3] = __float_as_uint(tf32_round(p3));
        }

        // ---- O += P V (A-frag built from C-frag via quad shuffles) ----
        #pragma unroll
        for (int j = 0; j < 8; j++) {
            uint32_t a[4];
            uint32_t x0 = __shfl_sync(0xffffffffu, pc[j][0], srcA);
            uint32_t x1 = __shfl_sync(0xffffffffu, pc[j][1], srcA);
            uint32_t x2 = __shfl_sync(0xffffffffu, pc[j][2], srcA);
            uint32_t x3 = __shfl_sync(0xffffffffu, pc[j][3], srcA);
            a[0] = selo ? x1 : x0;
            a[1] = selo ? x3 : x2;
            uint32_t y0 = __shfl_sync(0xffffffffu, pc[j][0], srcB);
            uint32_t y1 = __shfl_sync(0xffffffffu, pc[j][1], srcB);
            uint32_t y2 = __shfl_sync(0xffffffffu, pc[j][2], srcB);
            uint32_t y3 = __shfl_sync(0xffffffffu, pc[j][3], srcB);
            a[2] = selo ? y1 : y0;
            a[3] = selo ? y3 : y2;

            const float* v0 = Vs + (j * 8 + t) * VSTR + g;
            const float* v1 = v0 + 4 * VSTR;
            #pragma unroll
            for (int d = 0; d < 16; d++) {
                uint32_t b[2];
                b[0] = __float_as_uint(v0[d * 8]);
                b[1] = __float_as_uint(v1[d * 8]);
                mma_tf32(o[d], a, b);
            }
        }

        __syncthreads();
        if (kb + 2 < nkb) load_kv(kb & 1, kb + 2);
        CP_COMMIT();
    }

    // ---- finalize: reduce l across quad, normalize, write (tf32-rounded) ----
    l0 += __shfl_xor_sync(0xffffffffu, l0, 1);
    l0 += __shfl_xor_sync(0xffffffffu, l0, 2);
    l1 += __shfl_xor_sync(0xffffffffu, l1, 1);
    l1 += __shfl_xor_sync(0xffffffffu, l1, 2);
    const float inv0 = 1.0f / l0;
    const float inv1 = 1.0f / l1;

    float* op0 = out + (size_t)r0 * NQ + h * HEAD_DIM + 2 * t;
    float* op1 = out + (size_t)r1 * NQ + h * HEAD_DIM + 2 * t;
    #pragma unroll
    for (int d = 0; d < 16; d++) {
        float2 v0 = make_float2(tf32_round(o[d][0] * inv0), tf32_round(o[d][1] * inv0));
        float2 v1 = make_float2(tf32_round(o[d][2] * inv1), tf32_round(o[d][3] * inv1));
        *(float2*)(op0 + d * 8) = v0;
        *(float2*)(op1 + d * 8) = v1;
    }
}

// ---------------------------------------------------------------------------
// Launch
// ---------------------------------------------------------------------------
extern "C" void kernel_launch(void* const* d_in, const int* in_sizes, int n_in,
                              void* d_out, int out_size)
{
    const float* hidden = (const float*)d_in[0];
    const float* cosb   = (const float*)d_in[1];
    const float* sinb   = (const float*)d_in[2];
    const float* w_qkv  = (const float*)d_in[3];
    const float* b_qkv  = (const float*)d_in[4];
    const float* w_o    = (const float*)d_in[5];
    float* out = (float*)d_out;

    float *qkv = nullptr, *attn = nullptr, *Ar = nullptr, *Br = nullptr;
    cudaGetSymbolAddress((void**)&qkv,  g_qkv);
    cudaGetSymbolAddress((void**)&attn, g_attn);
    cudaGetSymbolAddress((void**)&Ar,   g_Ar);
    cudaGetSymbolAddress((void**)&Br,   g_Br);

    cudaFuncSetAttribute(gemm_mma<true>,  cudaFuncAttributeMaxDynamicSharedMemorySize, GSMEM_BYTES);
    cudaFuncSetAttribute(gemm_mma<false>, cudaFuncAttributeMaxDynamicSharedMemorySize, GSMEM_BYTES);
    cudaFuncSetAttribute(flash_tc,        cudaFuncAttributeMaxDynamicSharedMemorySize, FSMEM_BYTES);

    // 0) tf32-round GEMM1 operands
    {
        int n4 = SEQLEN * HIDDEN / 4;
        round_tf32_kernel<<<(n4 + 255) / 256, 256>>>(hidden, Ar, n4);
        n4 = HIDDEN * QKV_OUT / 4;
        round_tf32_kernel<<<(n4 + 255) / 256, 256>>>(w_qkv, Br, n4);
    }

    // 1) QKV projection + bias (tf32 mma.sync)
    gemm_mma<true><<<dim3(QKV_OUT / 128, SEQLEN / 128), 256, GSMEM_BYTES>>>(
        Ar, Br, b_qkv, qkv, HIDDEN, QKV_OUT, QKV_OUT);

    // 2) RoPE in-place on q + k
    {
        int total = SEQLEN * (NUM_HEADS + NUM_KV_HEADS) * 32;
        rope_kernel<<<(total + 255) / 256, 256>>>(cosb, sinb);
    }

    // 3) tf32-round the whole qkv buffer in-place (K/V become mma operands)
    {
        int n4 = SEQLEN * QKV_OUT / 4;
        round_tf32_kernel<<<(n4 + 255) / 256, 256>>>(qkv, qkv, n4);
    }

    // 4) causal GQA flash attention on tensor cores
    flash_tc<<<dim3(SEQLEN / FBM, NUM_HEADS), 256, FSMEM_BYTES>>>(attn);

    // 5) tf32-round w_o (stream-ordered after GEMM1: safe to reuse Br)
    {
        int n4 = NQ * HIDDEN / 4;
        round_tf32_kernel<<<(n4 + 255) / 256, 256>>>(w_o, Br, n4);
    }

    // 6) output projection (tf32 mma.sync)
    gemm_mma<false><<<dim3(HIDDEN / 128, SEQLEN / 128), 256, GSMEM_BYTES>>>(
        attn, Br, nullptr, out, NQ, HIDDEN, HIDDEN);
}

// round 6
// speedup vs baseline: 3.8985x; 1.0936x over previous
#include <cuda_runtime.h>
#include <cstdint>
#include <math.h>

#define SEQLEN   2048
#define HIDDEN   4096
#define NUM_HEADS 32
#define NUM_KV_HEADS 2
#define HEAD_DIM 128
#define QKV_OUT  ((NUM_HEADS + 2 * NUM_KV_HEADS) * HEAD_DIM)   // 4608
#define NQ       (NUM_HEADS * HEAD_DIM)                        // 4096
#define NKV      (NUM_KV_HEADS * HEAD_DIM)                     // 256
#define REP      (NUM_HEADS / NUM_KV_HEADS)                    // 16

// Scratch (device globals; no allocation allowed in kernel_launch)
__device__ float g_qkv[SEQLEN * QKV_OUT];        // ~37.7 MB
__device__ float g_attn[SEQLEN * NQ];            // ~33.5 MB
__device__ float g_Ar[SEQLEN * HIDDEN];          // 32 MB  (tf32-rounded A)
__device__ float g_Br[HIDDEN * QKV_OUT];         // 72 MB  (tf32-rounded B)

// ===========================================================================
// helpers
// ===========================================================================
__device__ __forceinline__ float tf32_round(float f) {
    uint32_t u;
    asm("cvt.rna.tf32.f32 %0, %1;" : "=r"(u) : "f"(f));
    return __uint_as_float(u);
}
__device__ __forceinline__ uint32_t smem_u32(const void* p) {
    uint32_t a;
    asm("{ .reg .u64 t; cvta.to.shared.u64 t, %1; cvt.u32.u64 %0, t; }"
        : "=r"(a) : "l"(p));
    return a;
}
__device__ __forceinline__ void cp_async16(uint32_t dst, const void* src) {
    asm volatile("cp.async.cg.shared.global [%0], [%1], 16;" :: "r"(dst), "l"(src));
}
#define CP_COMMIT() asm volatile("cp.async.commit_group;" ::: "memory")
#define CP_WAIT1()  asm volatile("cp.async.wait_group 1;" ::: "memory")

__device__ __forceinline__ void mma_tf32(float* c, const uint32_t* a, const uint32_t* b) {
    asm volatile(
        "mma.sync.aligned.m16n8k8.row.col.f32.tf32.tf32.f32 "
        "{%0,%1,%2,%3}, {%4,%5,%6,%7}, {%8,%9}, {%0,%1,%2,%3};"
        : "+f"(c[0]), "+f"(c[1]), "+f"(c[2]), "+f"(c[3])
        : "r"(a[0]), "r"(a[1]), "r"(a[2]), "r"(a[3]), "r"(b[0]), "r"(b[1]));
}

// ===========================================================================
// elementwise tf32 rounding pass (float4 vectorized; in-place allowed)
// ===========================================================================
__global__ void round_tf32_kernel(const float* __restrict__ in,
                                  float* __restrict__ out, int n4)
{
    int i = blockIdx.x * blockDim.x + threadIdx.x;
    if (i >= n4) return;
    float4 v = ((const float4*)in)[i];
    v.x = tf32_round(v.x); v.y = tf32_round(v.y);
    v.z = tf32_round(v.z); v.w = tf32_round(v.w);
    ((float4*)out)[i] = v;
}

// ===========================================================================
// Fused RoPE (interleaved, rot=64, q heads 0..31 + k heads 32..33) + tf32
// rounding of the ENTIRE qkv buffer, one float2 per thread, in-place.
// ===========================================================================
__global__ void rope_round_kernel(const float* __restrict__ cosb,
                                  const float* __restrict__ sinb)
{
    const int HALF = QKV_OUT / 2;
    int idx = blockIdx.x * blockDim.x + threadIdx.x;
    if (idx >= SEQLEN * HALF) return;
    int s = idx / HALF;
    int c = (idx - s * HALF) * 2;
    float2* p = (float2*)(g_qkv + (size_t)s * QKV_OUT + c);
    float2 v = *p;
    int head = c >> 7, dim = c & 127;
    if (head < NUM_HEADS + NUM_KV_HEADS && dim < 64) {
        int pair = dim >> 1;
        float cs = cosb[s * 64 + pair];
        float sn = sinb[s * 64 + pair];
        float x0 = v.x, x1 = v.y;
        v.x = x0 * cs - x1 * sn;
        v.y = x1 * cs + x0 * sn;
    }
    v.x = tf32_round(v.x);
    v.y = tf32_round(v.y);
    *p = v;
}

// ===========================================================================
// tf32 mma.sync GEMM: C[M,N] = A[M,K] @ B[K,N] (+bias)
// 3-stage cp.async, ONE sync per iter, loads overlap compute.
// ===========================================================================
#define ASTR 36
#define BSTR 136
#define A_FL (128 * ASTR)
#define B_FL (32 * BSTR)
#define STAGE_FL (A_FL + B_FL)
#define GSMEM_BYTES (3 * STAGE_FL * 4)

template <bool HAS_BIAS>
__global__ __launch_bounds__(256)
void gemm_mma(const float* __restrict__ A, const float* __restrict__ B,
              const float* __restrict__ bias, float* __restrict__ C,
              int K, int ldb, int N)
{
    extern __shared__ float smem[];
    const uint32_t sbase = smem_u32(smem);

    const int tid  = threadIdx.x;
    const int warp = tid >> 5;
    const int lane = tid & 31;
    const int g    = lane >> 2;
    const int t    = lane & 3;
    const int wm   = warp & 1;
    const int wn   = warp >> 1;
    const int brow = blockIdx.y * 128;
    const int n0   = blockIdx.x * 128;

    auto load_stage = [&](int s, int k0) {
        const float* Ap = A + (size_t)brow * K + k0;
        const float* Bp = B + (size_t)k0 * ldb + n0;
        const uint32_t sA = sbase + (uint32_t)s * (STAGE_FL * 4);
        const uint32_t sB = sA + A_FL * 4;
        #pragma unroll
        for (int p = 0; p < 4; p++) {
            int id = tid + p * 256;
            int r = id >> 3, c = (id & 7) << 2;
            cp_async16(sA + (uint32_t)(r * ASTR + c) * 4, Ap + (size_t)r * K + c);
        }
        #pragma unroll
        for (int p = 0; p < 4; p++) {
            int id = tid + p * 256;
            int r = id >> 5, c = (id & 31) << 2;
            cp_async16(sB + (uint32_t)(r * BSTR + c) * 4, Bp + (size_t)r * ldb + c);
        }
    };

    const int iters = K / 32;
    load_stage(0, 0);  CP_COMMIT();
    load_stage(1, 32); CP_COMMIT();

    float acc[4][4][4];
    #pragma unroll
    for (int mt = 0; mt < 4; mt++)
        #pragma unroll
        for (int nt = 0; nt < 4; nt++)
            #pragma unroll
            for (int q = 0; q < 4; q++) acc[mt][nt][q] = 0.0f;

    for (int i = 0; i < iters; i++) {
        CP_WAIT1();
        __syncthreads();
        // stage (i+2)%3 == (i-1)%3 is free after the barrier: issue next loads
        // NOW so they overlap the whole mma body.
        if (i + 2 < iters) load_stage((i + 2) % 3, (i + 2) * 32);
        CP_COMMIT();

        const float* As = smem + (i % 3) * STAGE_FL;
        const float* Bs = As + A_FL;

        #pragma unroll
        for (int kk = 0; kk < 4; kk++) {
            const int k = kk * 8;
            uint32_t a[4][4];
            #pragma unroll
            for (int mt = 0; mt < 4; mt++) {
                const float* ap = As + (wm * 64 + mt * 16 + g) * ASTR + k + t;
                a[mt][0] = __float_as_uint(ap[0]);
                a[mt][1] = __float_as_uint(ap[8 * ASTR]);
                a[mt][2] = __float_as_uint(ap[4]);
                a[mt][3] = __float_as_uint(ap[8 * ASTR + 4]);
            }
            uint32_t b[4][2];
            #pragma unroll
            for (int nt = 0; nt < 4; nt++) {
                const float* bp = Bs + (k + t) * BSTR + wn * 32 + nt * 8 + g;
                b[nt][0] = __float_as_uint(bp[0]);
                b[nt][1] = __float_as_uint(bp[4 * BSTR]);
            }
            #pragma unroll
            for (int mt = 0; mt < 4; mt++)
                #pragma unroll
                for (int nt = 0; nt < 4; nt++)
                    mma_tf32(acc[mt][nt], a[mt], b[nt]);
        }
    }

    #pragma unroll
    for (int mt = 0; mt < 4; mt++) {
        #pragma unroll
        for (int nt = 0; nt < 4; nt++) {
            const int row = brow + wm * 64 + mt * 16 + g;
            const int col = n0 + wn * 32 + nt * 8 + 2 * t;
            float bx = 0.f, by = 0.f;
            if (HAS_BIAS) { bx = bias[col]; by = bias[col + 1]; }
            float2 v0 = make_float2(acc[mt][nt][0] + bx, acc[mt][nt][1] + by);
            float2 v1 = make_float2(acc[mt][nt][2] + bx, acc[mt][nt][3] + by);
            *(float2*)&C[(size_t)row * N + col]       = v0;
            *(float2*)&C[(size_t)(row + 8) * N + col] = v1;
        }
    }
}

// ===========================================================================
// Flash attention (causal, GQA rep=16) on tensor cores (tf32 mma.sync).
// BM=128 q rows (8 warps x 16), BN=64 keys/iter, K/V 3-stage cp.async,
// ONE sync per iter, loads overlap compute. Q-blocks scheduled big-first.
// ===========================================================================
#define FBM 128
#define FBN 64
#define KSTR 132
#define VSTR 136
#define FSTAGE_FL (FBN * KSTR + FBN * VSTR)     // 17152 floats
#define FSMEM_BYTES (3 * FSTAGE_FL * 4)         // 205824 bytes

__global__ __launch_bounds__(256, 1) void flash_tc(float* __restrict__ out)
{
    extern __shared__ float fs[];
    const uint32_t sbase = smem_u32(fs);

    const int tid  = threadIdx.x;
    const int warp = tid >> 5;
    const int lane = tid & 31;
    const int g    = lane >> 2;
    const int t    = lane & 3;
    const int h    = blockIdx.y;
    const int kvh  = h / REP;
    const int qi   = gridDim.x - 1 - blockIdx.x;   // big blocks first
    const int q0   = qi * FBM;
    const int r0   = q0 + warp * 16 + g;
    const int r1   = r0 + 8;
    const float scale = 0.08838834764831845f;

    // ---- Q fragments, pre-scaled + tf32-rounded, resident in registers ----
    uint32_t qa[16][4];
    {
        const float* qb = g_qkv + (size_t)(q0 + warp * 16) * QKV_OUT + h * HEAD_DIM;
        #pragma unroll
        for (int ks = 0; ks < 16; ks++) {
            qa[ks][0] = __float_as_uint(tf32_round(qb[(size_t)g       * QKV_OUT + ks * 8 + t]     * scale));
            qa[ks][1] = __float_as_uint(tf32_round(qb[(size_t)(g + 8) * QKV_OUT + ks * 8 + t]     * scale));
            qa[ks][2] = __float_as_uint(tf32_round(qb[(size_t)g       * QKV_OUT + ks * 8 + t + 4] * scale));
            qa[ks][3] = __float_as_uint(tf32_round(qb[(size_t)(g + 8) * QKV_OUT + ks * 8 + t + 4] * scale));
        }
    }

    auto load_kv = [&](int s, int kb) {
        const uint32_t sK = sbase + (uint32_t)s * (FSTAGE_FL * 4);
        const uint32_t sV = sK + FBN * KSTR * 4;
        const float* src = g_qkv + (size_t)(kb * FBN) * QKV_OUT + NQ + kvh * HEAD_DIM;
        #pragma unroll
        for (int p = 0; p < 8; p++) {
            int id = tid + p * 256;
            int r = id >> 5;
            int c = (id & 31) << 2;
            const float* rp = src + (size_t)r * QKV_OUT + c;
            cp_async16(sK + (uint32_t)(r * KSTR + c) * 4, rp);
            cp_async16(sV + (uint32_t)(r * VSTR + c) * 4, rp + NKV);
        }
    };

    float o[16][4];
    #pragma unroll
    for (int d = 0; d < 16; d++)
        #pragma unroll
        for (int q = 0; q < 4; q++) o[d][q] = 0.0f;
    float m0 = -1e30f, m1 = -1e30f, l0 = 0.0f, l1 = 0.0f;

    const int nkb = (q0 + FBM) / FBN;
    load_kv(0, 0); CP_COMMIT();
    load_kv(1, 1); CP_COMMIT();

    const int srcA = (lane & ~3) | (t >> 1);
    const int srcB = srcA + 2;
    const int selo = t & 1;

    for (int kb = 0; kb < nkb; kb++) {
        CP_WAIT1();
        __syncthreads();
        // stage (kb+2)%3 == (kb-1)%3 is free after the barrier: issue loads
        // now so they overlap the mma/softmax body.
        if (kb + 2 < nkb) load_kv((kb + 2) % 3, kb + 2);
        CP_COMMIT();

        const float* Ks = fs + (kb % 3) * FSTAGE_FL;
        const float* Vs = Ks + FBN * KSTR;

        // ---- S = Q K^T (scaled) ----
        float sc[8][4];
        #pragma unroll
        for (int j = 0; j < 8; j++)
            #pragma unroll
            for (int q = 0; q < 4; q++) sc[j][q] = 0.0f;

        #pragma unroll
        for (int ks = 0; ks < 16; ks++) {
            const int kd = ks * 8;
            #pragma unroll
            for (int j = 0; j < 8; j++) {
                uint32_t b[2];
                const float* kp = Ks + (j * 8 + g) * KSTR + kd + t;
                b[0] = __float_as_uint(kp[0]);
                b[1] = __float_as_uint(kp[4]);
                mma_tf32(sc[j], qa[ks], b);
            }
        }

        // ---- causal mask (only needed on the last two k-blocks) ----
        if (kb >= nkb - 2) {
            const int keyb = kb * FBN + 2 * t;
            #pragma unroll
            for (int j = 0; j < 8; j++) {
                int k0 = keyb + j * 8;
                if (k0     > r0) sc[j][0] = -1e30f;
                if (k0 + 1 > r0) sc[j][1] = -1e30f;
                if (k0     > r1) sc[j][2] = -1e30f;
                if (k0 + 1 > r1) sc[j][3] = -1e30f;
            }
        }

        // ---- online softmax ----
        float mx0 = -1e30f, mx1 = -1e30f;
        #pragma unroll
        for (int j = 0; j < 8; j++) {
            mx0 = fmaxf(mx0, fmaxf(sc[j][0], sc[j][1]));
            mx1 = fmaxf(mx1, fmaxf(sc[j][2], sc[j][3]));
        }
        mx0 = fmaxf(mx0, __shfl_xor_sync(0xffffffffu, mx0, 1));
        mx0 = fmaxf(mx0, __shfl_xor_sync(0xffffffffu, mx0, 2));
        mx1 = fmaxf(mx1, __shfl_xor_sync(0xffffffffu, mx1, 1));
        mx1 = fmaxf(mx1, __shfl_xor_sync(0xffffffffu, mx1, 2));
        const float mn0 = fmaxf(m0, mx0);
        const float mn1 = fmaxf(m1, mx1);
        const float c0 = __expf(m0 - mn0);
        const float c1 = __expf(m1 - mn1);
        m0 = mn0; m1 = mn1;
        l0 *= c0;  l1 *= c1;
        #pragma unroll
        for (int d = 0; d < 16; d++) {
            o[d][0] *= c0; o[d][1] *= c0;
            o[d][2] *= c1; o[d][3] *= c1;
        }

        uint32_t pc[8][4];
        #pragma unroll
        for (int j = 0; j < 8; j++) {
            float p0 = __expf(sc[j][0] - m0);
            float p1 = __expf(sc[j][1] - m0);
            float p2 = __expf(sc[j][2] - m1);
            float p3 = __expf(sc[j][3] - m1);
            l0 += p0 + p1;
            l1 += p2 + p3;
            pc[j][0] = __float_as_uint(tf32_round(p0));
            pc[j][1] = __float_as_uint(tf32_round(p1));
            pc[j][2] = __float_as_uint(tf32_round(p2));
            pc[j][3] = __float_as_uint(tf32_round(p3));
        }

        // ---- O += P V (A-frag built from C-frag via quad shuffles) ----
        #pragma unroll
        for (int j = 0; j < 8; j++) {
            uint32_t a[4];
            uint32_t x0 = __shfl_sync(0xffffffffu, pc[j][0], srcA);
            uint32_t x1 = __shfl_sync(0xffffffffu, pc[j][1], srcA);
            uint32_t x2 = __shfl_sync(0xffffffffu, pc[j][2], srcA);
            uint32_t x3 = __shfl_sync(0xffffffffu, pc[j][3], srcA);
            a[0] = selo ? x1 : x0;
            a[1] = selo ? x3 : x2;
            uint32_t y0 = __shfl_sync(0xffffffffu, pc[j][0], srcB);
            uint32_t y1 = __shfl_sync(0xffffffffu, pc[j][1], srcB);
            uint32_t y2 = __shfl_sync(0xffffffffu, pc[j][2], srcB);
            uint32_t y3 = __shfl_sync(0xffffffffu, pc[j][3], srcB);
            a[2] = selo ? y1 : y0;
            a[3] = selo ? y3 : y2;

            const float* v0 = Vs + (j * 8 + t) * VSTR + g;
            const float* v1 = v0 + 4 * VSTR;
            #pragma unroll
            for (int d = 0; d < 16; d++) {
                uint32_t b[2];
                b[0] = __float_as_uint(v0[d * 8]);
                b[1] = __float_as_uint(v1[d * 8]);
                mma_tf32(o[d], a, b);
            }
        }
    }

    // ---- finalize ----
    l0 += __shfl_xor_sync(0xffffffffu, l0, 1);
    l0 += __shfl_xor_sync(0xffffffffu, l0, 2);
    l1 += __shfl_xor_sync(0xffffffffu, l1, 1);
    l1 += __shfl_xor_sync(0xffffffffu, l1, 2);
    const float inv0 = 1.0f / l0;
    const float inv1 = 1.0f / l1;

    float* op0 = out + (size_t)r0 * NQ + h * HEAD_DIM + 2 * t;
    float* op1 = out + (size_t)r1 * NQ + h * HEAD_DIM + 2 * t;
    #pragma unroll
    for (int d = 0; d < 16; d++) {
        float2 v0 = make_float2(tf32_round(o[d][0] * inv0), tf32_round(o[d][1] * inv0));
        float2 v1 = make_float2(tf32_round(o[d][2] * inv1), tf32_round(o[d][3] * inv1));
        *(float2*)(op0 + d * 8) = v0;
        *(float2*)(op1 + d * 8) = v1;
    }
}

// ---------------------------------------------------------------------------
// Launch
// ---------------------------------------------------------------------------
extern "C" void kernel_launch(void* const* d_in, const int* in_sizes, int n_in,
                              void* d_out, int out_size)
{
    const float* hidden = (const float*)d_in[0];
    const float* cosb   = (const float*)d_in[1];
    const float* sinb   = (const float*)d_in[2];
    const float* w_qkv  = (const float*)d_in[3];
    const float* b_qkv  = (const float*)d_in[4];
    const float* w_o    = (const float*)d_in[5];
    float* out = (float*)d_out;

    float *qkv = nullptr, *attn = nullptr, *Ar = nullptr, *Br = nullptr;
    cudaGetSymbolAddress((void**)&qkv,  g_qkv);
    cudaGetSymbolAddress((void**)&attn, g_attn);
    cudaGetSymbolAddress((void**)&Ar,   g_Ar);
    cudaGetSymbolAddress((void**)&Br,   g_Br);

    cudaFuncSetAttribute(gemm_mma<true>,  cudaFuncAttributeMaxDynamicSharedMemorySize, GSMEM_BYTES);
    cudaFuncSetAttribute(gemm_mma<false>, cudaFuncAttributeMaxDynamicSharedMemorySize, GSMEM_BYTES);
    cudaFuncSetAttribute(flash_tc,        cudaFuncAttributeMaxDynamicSharedMemorySize, FSMEM_BYTES);

    // 0) tf32-round GEMM1 operands
    {
        int n4 = SEQLEN * HIDDEN / 4;
        round_tf32_kernel<<<(n4 + 255) / 256, 256>>>(hidden, Ar, n4);
        n4 = HIDDEN * QKV_OUT / 4;
        round_tf32_kernel<<<(n4 + 255) / 256, 256>>>(w_qkv, Br, n4);
    }

    // 1) QKV projection + bias (tf32 mma.sync)
    gemm_mma<true><<<dim3(QKV_OUT / 128, SEQLEN / 128), 256, GSMEM_BYTES>>>(
        Ar, Br, b_qkv, qkv, HIDDEN, QKV_OUT, QKV_OUT);

    // 2) fused RoPE + tf32-round over the whole qkv buffer (in place)
    {
        int total = SEQLEN * (QKV_OUT / 2);
        rope_round_kernel<<<(total + 255) / 256, 256>>>(cosb, sinb);
    }

    // 3) causal GQA flash attention on tensor cores
    flash_tc<<<dim3(SEQLEN / FBM, NUM_HEADS), 256, FSMEM_BYTES>>>(attn);

    // 4) tf32-round w_o (stream-ordered after GEMM1: safe to reuse Br)
    {
        int n4 = NQ * HIDDEN / 4;
        round_tf32_kernel<<<(n4 + 255) / 256, 256>>>(w_o, Br, n4);
    }

    // 5) output projection (tf32 mma.sync)
    gemm_mma<false><<<dim3(HIDDEN / 128, SEQLEN / 128), 256, GSMEM_BYTES>>>(
        attn, Br, nullptr, out, NQ, HIDDEN, HIDDEN);
}

// round 8
// speedup vs baseline: 4.2416x; 1.0880x over previous
#include <cuda_runtime.h>
#include <cstdint>
#include <math.h>

#define SEQLEN   2048
#define HIDDEN   4096
#define NUM_HEADS 32
#define NUM_KV_HEADS 2
#define HEAD_DIM 128
#define QKV_OUT  ((NUM_HEADS + 2 * NUM_KV_HEADS) * HEAD_DIM)   // 4608
#define NQ       (NUM_HEADS * HEAD_DIM)                        // 4096
#define NKV      (NUM_KV_HEADS * HEAD_DIM)                     // 256
#define REP      (NUM_HEADS / NUM_KV_HEADS)                    // 16

// Scratch (device globals; no allocation allowed in kernel_launch)
__device__ float g_qkv[SEQLEN * QKV_OUT];        // ~37.7 MB
__device__ float g_attn[SEQLEN * NQ];            // ~33.5 MB
__device__ float g_Ar[SEQLEN * HIDDEN];          // 32 MB  (tf32-rounded A)
__device__ float g_Br[HIDDEN * QKV_OUT];         // 72 MB  (tf32-rounded B)
__device__ float g_vt[NUM_KV_HEADS * HEAD_DIM * SEQLEN];  // 2 MB, V dim-major

// ===========================================================================
// helpers
// ===========================================================================
__device__ __forceinline__ float tf32_round(float f) {
    uint32_t u;
    asm("cvt.rna.tf32.f32 %0, %1;" : "=r"(u) : "f"(f));
    return __uint_as_float(u);
}
__device__ __forceinline__ uint32_t smem_u32(const void* p) {
    uint32_t a;
    asm("{ .reg .u64 t; cvta.to.shared.u64 t, %1; cvt.u32.u64 %0, t; }"
        : "=r"(a) : "l"(p));
    return a;
}
__device__ __forceinline__ void cp_async16(uint32_t dst, const void* src) {
    asm volatile("cp.async.cg.shared.global [%0], [%1], 16;" :: "r"(dst), "l"(src));
}
#define CP_COMMIT() asm volatile("cp.async.commit_group;" ::: "memory")
#define CP_WAIT1()  asm volatile("cp.async.wait_group 1;" ::: "memory")

__device__ __forceinline__ void mma_tf32(float* c, const uint32_t* a, const uint32_t* b) {
    asm volatile(
        "mma.sync.aligned.m16n8k8.row.col.f32.tf32.tf32.f32 "
        "{%0,%1,%2,%3}, {%4,%5,%6,%7}, {%8,%9}, {%0,%1,%2,%3};"
        : "+f"(c[0]), "+f"(c[1]), "+f"(c[2]), "+f"(c[3])
        : "r"(a[0]), "r"(a[1]), "r"(a[2]), "r"(a[3]), "r"(b[0]), "r"(b[1]));
}
__device__ __forceinline__ void ldsm_x4(uint32_t& r0, uint32_t& r1,
                                        uint32_t& r2, uint32_t& r3, uint32_t addr) {
    asm volatile("ldmatrix.sync.aligned.m8n8.x4.shared.b16 {%0,%1,%2,%3}, [%4];"
        : "=r"(r0), "=r"(r1), "=r"(r2), "=r"(r3) : "r"(addr));
}

// ===========================================================================
// elementwise tf32 rounding pass (float4 vectorized; in-place allowed)
// ===========================================================================
__global__ void round_tf32_kernel(const float* __restrict__ in,
                                  float* __restrict__ out, int n4)
{
    int i = blockIdx.x * blockDim.x + threadIdx.x;
    if (i >= n4) return;
    float4 v = ((const float4*)in)[i];
    v.x = tf32_round(v.x); v.y = tf32_round(v.y);
    v.z = tf32_round(v.z); v.w = tf32_round(v.w);
    ((float4*)out)[i] = v;
}

// ===========================================================================
// Fused RoPE + tf32 rounding of qkv (in place) + dim-major V copy to g_vt.
// ===========================================================================
__global__ void rope_round_kernel(const float* __restrict__ cosb,
                                  const float* __restrict__ sinb)
{
    const int HALF = QKV_OUT / 2;
    int idx = blockIdx.x * blockDim.x + threadIdx.x;
    if (idx >= SEQLEN * HALF) return;
    int s = idx / HALF;
    int c = (idx - s * HALF) * 2;
    float2* p = (float2*)(g_qkv + (size_t)s * QKV_OUT + c);
    float2 v = *p;
    int head = c >> 7, dim = c & 127;
    if (head < NUM_HEADS + NUM_KV_HEADS && dim < 64) {
        int pair = dim >> 1;
        float cs = cosb[s * 64 + pair];
        float sn = sinb[s * 64 + pair];
        float x0 = v.x, x1 = v.y;
        v.x = x0 * cs - x1 * sn;
        v.y = x1 * cs + x0 * sn;
    }
    v.x = tf32_round(v.x);
    v.y = tf32_round(v.y);
    *p = v;
    if (head >= NUM_HEADS + NUM_KV_HEADS) {   // V heads -> dim-major copy
        int kvh = head - (NUM_HEADS + NUM_KV_HEADS);
        g_vt[((size_t)(kvh * HEAD_DIM + dim))     * SEQLEN + s] = v.x;
        g_vt[((size_t)(kvh * HEAD_DIM + dim + 1)) * SEQLEN + s] = v.y;
    }
}

// ===========================================================================
// tf32 mma.sync GEMM: C[M,N] = A[M,K] @ B[K,N] (+bias)
// 3-stage cp.async, one sync/iter, ldmatrix for A fragments.
// ===========================================================================
#define ASTR 36
#define BSTR 136
#define A_FL (128 * ASTR)
#define B_FL (32 * BSTR)
#define STAGE_FL (A_FL + B_FL)
#define GSMEM_BYTES (3 * STAGE_FL * 4)

template <bool HAS_BIAS>
__global__ __launch_bounds__(256)
void gemm_mma(const float* __restrict__ A, const float* __restrict__ B,
              const float* __restrict__ bias, float* __restrict__ C,
              int K, int ldb, int N)
{
    extern __shared__ float smem[];
    const uint32_t sbase = smem_u32(smem);

    const int tid  = threadIdx.x;
    const int warp = tid >> 5;
    const int lane = tid & 31;
    const int g    = lane >> 2;
    const int t    = lane & 3;
    const int wm   = warp & 1;
    const int wn   = warp >> 1;
    const int brow = blockIdx.y * 128;
    const int n0   = blockIdx.x * 128;

    // ldmatrix lane->row/col mapping for A fragments
    const int ga_row = lane & 15;
    const int ga_col = (lane >> 4) << 2;

    auto load_stage = [&](int s, int k0) {
        const float* Ap = A + (size_t)brow * K + k0;
        const float* Bp = B + (size_t)k0 * ldb + n0;
        const uint32_t sA = sbase + (uint32_t)s * (STAGE_FL * 4);
        const uint32_t sB = sA + A_FL * 4;
        #pragma unroll
        for (int p = 0; p < 4; p++) {
            int id = tid + p * 256;
            int r = id >> 3, c = (id & 7) << 2;
            cp_async16(sA + (uint32_t)(r * ASTR + c) * 4, Ap + (size_t)r * K + c);
        }
        #pragma unroll
        for (int p = 0; p < 4; p++) {
            int id = tid + p * 256;
            int r = id >> 5, c = (id & 31) << 2;
            cp_async16(sB + (uint32_t)(r * BSTR + c) * 4, Bp + (size_t)r * ldb + c);
        }
    };

    const int iters = K / 32;
    load_stage(0, 0);  CP_COMMIT();
    load_stage(1, 32); CP_COMMIT();

    float acc[4][4][4];
    #pragma unroll
    for (int mt = 0; mt < 4; mt++)
        #pragma unroll
        for (int nt = 0; nt < 4; nt++)
            #pragma unroll
            for (int q = 0; q < 4; q++) acc[mt][nt][q] = 0.0f;

    for (int i = 0; i < iters; i++) {
        CP_WAIT1();
        __syncthreads();
        if (i + 2 < iters) load_stage((i + 2) % 3, (i + 2) * 32);
        CP_COMMIT();

        const uint32_t sA = sbase + (uint32_t)(i % 3) * (STAGE_FL * 4);
        const float* Bs = smem + (i % 3) * STAGE_FL + A_FL;

        #pragma unroll
        for (int kk = 0; kk < 4; kk++) {
            const int k = kk * 8;
            uint32_t a[4][4];
            #pragma unroll
            for (int mt = 0; mt < 4; mt++) {
                uint32_t addr = sA + (uint32_t)((wm * 64 + mt * 16 + ga_row) * ASTR + k + ga_col) * 4;
                ldsm_x4(a[mt][0], a[mt][1], a[mt][2], a[mt][3], addr);
            }
            uint32_t b[4][2];
            #pragma unroll
            for (int nt = 0; nt < 4; nt++) {
                const float* bp = Bs + (k + t) * BSTR + wn * 32 + nt * 8 + g;
                b[nt][0] = __float_as_uint(bp[0]);
                b[nt][1] = __float_as_uint(bp[4 * BSTR]);
            }
            #pragma unroll
            for (int mt = 0; mt < 4; mt++)
                #pragma unroll
                for (int nt = 0; nt < 4; nt++)
                    mma_tf32(acc[mt][nt], a[mt], b[nt]);
        }
    }

    #pragma unroll
    for (int mt = 0; mt < 4; mt++) {
        #pragma unroll
        for (int nt = 0; nt < 4; nt++) {
            const int row = brow + wm * 64 + mt * 16 + g;
            const int col = n0 + wn * 32 + nt * 8 + 2 * t;
            float bx = 0.f, by = 0.f;
            if (HAS_BIAS) { bx = bias[col]; by = bias[col + 1]; }
            float2 v0 = make_float2(acc[mt][nt][0] + bx, acc[mt][nt][1] + by);
            float2 v1 = make_float2(acc[mt][nt][2] + bx, acc[mt][nt][3] + by);
            *(float2*)&C[(size_t)row * N + col]       = v0;
            *(float2*)&C[(size_t)(row + 8) * N + col] = v1;
        }
    }
}

// ===========================================================================
// Flash attention (causal, GQA rep=16), tf32 mma.sync + ldmatrix fragments.
// K tile smem [key][dim] (stride 132), V tile smem [dim][key] (stride 68,
// loaded dim-major from g_vt). 3-stage cp.async, one sync/iter.
// ===========================================================================
#define FBM 128
#define FBN 64
#define KSTR 132
#define VSTR2 68
#define K_FL (FBN * KSTR)            // 8448
#define V_FL (HEAD_DIM * VSTR2)      // 8704
#define FSTAGE_FL (K_FL + V_FL)      // 17152
#define FSMEM_BYTES (3 * FSTAGE_FL * 4)   // 205824

__global__ __launch_bounds__(256, 1) void flash_tc(float* __restrict__ out)
{
    extern __shared__ float fs[];
    const uint32_t sbase = smem_u32(fs);

    const int tid  = threadIdx.x;
    const int warp = tid >> 5;
    const int lane = tid & 31;
    const int g    = lane >> 2;
    const int t    = lane & 3;
    const int h    = blockIdx.y;
    const int kvh  = h / REP;
    const int qi   = gridDim.x - 1 - blockIdx.x;   // big blocks first
    const int q0   = qi * FBM;
    const int r0   = q0 + warp * 16 + g;
    const int r1   = r0 + 8;
    const float scale = 0.08838834764831845f;

    // ldmatrix lane mappings
    const int kq_row = (lane & 7) + ((lane >> 4) << 3);   // key offset 0..15
    const int kq_dim = ((lane >> 3) & 1) << 2;            // 0 or 4
    const int pv_dim = (lane & 7) + ((lane >> 4) << 3);   // dim offset 0..15
    const int pv_key = ((lane >> 3) & 1) << 2;            // 0 or 4

    // ---- Q fragments, pre-scaled + tf32-rounded, resident in registers ----
    uint32_t qa[16][4];
    {
        const float* qb = g_qkv + (size_t)(q0 + warp * 16) * QKV_OUT + h * HEAD_DIM;
        #pragma unroll
        for (int ks = 0; ks < 16; ks++) {
            qa[ks][0] = __float_as_uint(tf32_round(qb[(size_t)g       * QKV_OUT + ks * 8 + t]     * scale));
            qa[ks][1] = __float_as_uint(tf32_round(qb[(size_t)(g + 8) * QKV_OUT + ks * 8 + t]     * scale));
            qa[ks][2] = __float_as_uint(tf32_round(qb[(size_t)g       * QKV_OUT + ks * 8 + t + 4] * scale));
            qa[ks][3] = __float_as_uint(tf32_round(qb[(size_t)(g + 8) * QKV_OUT + ks * 8 + t + 4] * scale));
        }
    }

    auto load_kv = [&](int s, int kb) {
        const uint32_t sK = sbase + (uint32_t)s * (FSTAGE_FL * 4);
        const uint32_t sV = sK + K_FL * 4;
        const float* ksrc = g_qkv + (size_t)(kb * FBN) * QKV_OUT + NQ + kvh * HEAD_DIM;
        const float* vsrc = g_vt + (size_t)(kvh * HEAD_DIM) * SEQLEN + kb * FBN;
        #pragma unroll
        for (int p = 0; p < 8; p++) {
            int id = tid + p * 256;
            int r = id >> 5;             // key 0..63
            int c = (id & 31) << 2;      // dim 0..124
            cp_async16(sK + (uint32_t)(r * KSTR + c) * 4, ksrc + (size_t)r * QKV_OUT + c);
        }
        #pragma unroll
        for (int p = 0; p < 8; p++) {
            int id = tid + p * 256;
            int r = id >> 4;             // dim 0..127
            int c = (id & 15) << 2;      // key 0..60
            cp_async16(sV + (uint32_t)(r * VSTR2 + c) * 4, vsrc + (size_t)r * SEQLEN + c);
        }
    };

    float o[16][4];
    #pragma unroll
    for (int d = 0; d < 16; d++)
        #pragma unroll
        for (int q = 0; q < 4; q++) o[d][q] = 0.0f;
    float m0 = -1e30f, m1 = -1e30f, l0 = 0.0f, l1 = 0.0f;

    const int nkb = (q0 + FBM) / FBN;
    load_kv(0, 0); CP_COMMIT();
    load_kv(1, 1); CP_COMMIT();

    const int srcA = (lane & ~3) | (t >> 1);
    const int srcB = srcA + 2;
    const int selo = t & 1;

    for (int kb = 0; kb < nkb; kb++) {
        CP_WAIT1();
        __syncthreads();
        if (kb + 2 < nkb) load_kv((kb + 2) % 3, kb + 2);
        CP_COMMIT();

        const uint32_t sKu = sbase + (uint32_t)(kb % 3) * (FSTAGE_FL * 4);
        const uint32_t sVu = sKu + K_FL * 4;

        // ---- S = Q K^T (scaled); B-frags via ldmatrix.x4 (2 j-tiles/op) ----
        float sc[8][4];
        #pragma unroll
        for (int j = 0; j < 8; j++)
            #pragma unroll
            for (int q = 0; q < 4; q++) sc[j][q] = 0.0f;

        #pragma unroll
        for (int ks = 0; ks < 16; ks++) {
            #pragma unroll
            for (int jp = 0; jp < 4; jp++) {
                uint32_t b0, b1, b2, b3;
                uint32_t addr = sKu + (uint32_t)((jp * 16 + kq_row) * KSTR + ks * 8 + kq_dim) * 4;
                ldsm_x4(b0, b1, b2, b3, addr);
                uint32_t bb0[2] = { b0, b1 };
                uint32_t bb1[2] = { b2, b3 };
                mma_tf32(sc[2 * jp],     qa[ks], bb0);
                mma_tf32(sc[2 * jp + 1], qa[ks], bb1);
            }
        }

        // ---- causal mask (only needed on the last two k-blocks) ----
        if (kb >= nkb - 2) {
            const int keyb = kb * FBN + 2 * t;
            #pragma unroll
            for (int j = 0; j < 8; j++) {
                int k0 = keyb + j * 8;
                if (k0     > r0) sc[j][0] = -1e30f;
                if (k0 + 1 > r0) sc[j][1] = -1e30f;
                if (k0     > r1) sc[j][2] = -1e30f;
                if (k0 + 1 > r1) sc[j][3] = -1e30f;
            }
        }

        // ---- online softmax ----
        float mx0 = -1e30f, mx1 = -1e30f;
        #pragma unroll
        for (int j = 0; j < 8; j++) {
            mx0 = fmaxf(mx0, fmaxf(sc[j][0], sc[j][1]));
            mx1 = fmaxf(mx1, fmaxf(sc[j][2], sc[j][3]));
        }
        mx0 = fmaxf(mx0, __shfl_xor_sync(0xffffffffu, mx0, 1));
        mx0 = fmaxf(mx0, __shfl_xor_sync(0xffffffffu, mx0, 2));
        mx1 = fmaxf(mx1, __shfl_xor_sync(0xffffffffu, mx1, 1));
        mx1 = fmaxf(mx1, __shfl_xor_sync(0xffffffffu, mx1, 2));
        const float mn0 = fmaxf(m0, mx0);
        const float mn1 = fmaxf(m1, mx1);
        const float c0 = __expf(m0 - mn0);
        const float c1 = __expf(m1 - mn1);
        m0 = mn0; m1 = mn1;
        l0 *= c0;  l1 *= c1;
        #pragma unroll
        for (int d = 0; d < 16; d++) {
            o[d][0] *= c0; o[d][1] *= c0;
            o[d][2] *= c1; o[d][3] *= c1;
        }

        uint32_t pc[8][4];
        #pragma unroll
        for (int j = 0; j < 8; j++) {
            float p0 = __expf(sc[j][0] - m0);
            float p1 = __expf(sc[j][1] - m0);
            float p2 = __expf(sc[j][2] - m1);
            float p3 = __expf(sc[j][3] - m1);
            l0 += p0 + p1;
            l1 += p2 + p3;
            pc[j][0] = __float_as_uint(tf32_round(p0));
            pc[j][1] = __float_as_uint(tf32_round(p1));
            pc[j][2] = __float_as_uint(tf32_round(p2));
            pc[j][3] = __float_as_uint(tf32_round(p3));
        }

        // ---- O += P V; A-frag via quad shuffles, B-frag via ldmatrix.x4 ----
        #pragma unroll
        for (int j = 0; j < 8; j++) {
            uint32_t a[4];
            uint32_t x0 = __shfl_sync(0xffffffffu, pc[j][0], srcA);
            uint32_t x1 = __shfl_sync(0xffffffffu, pc[j][1], srcA);
            uint32_t x2 = __shfl_sync(0xffffffffu, pc[j][2], srcA);
            uint32_t x3 = __shfl_sync(0xffffffffu, pc[j][3], srcA);
            a[0] = selo ? x1 : x0;
            a[1] = selo ? x3 : x2;
            uint32_t y0 = __shfl_sync(0xffffffffu, pc[j][0], srcB);
            uint32_t y1 = __shfl_sync(0xffffffffu, pc[j][1], srcB);
            uint32_t y2 = __shfl_sync(0xffffffffu, pc[j][2], srcB);
            uint32_t y3 = __shfl_sync(0xffffffffu, pc[j][3], srcB);
            a[2] = selo ? y1 : y0;
            a[3] = selo ? y3 : y2;

            #pragma unroll
            for (int dp = 0; dp < 8; dp++) {
                uint32_t v0, v1, v2, v3;
                uint32_t addr = sVu + (uint32_t)((dp * 16 + pv_dim) * VSTR2 + j * 8 + pv_key) * 4;
                ldsm_x4(v0, v1, v2, v3, addr);
                uint32_t bb0[2] = { v0, v1 };
                uint32_t bb1[2] = { v2, v3 };
                mma_tf32(o[2 * dp],     a, bb0);
                mma_tf32(o[2 * dp + 1], a, bb1);
            }
        }
    }

    // ---- finalize ----
    l0 += __shfl_xor_sync(0xffffffffu, l0, 1);
    l0 += __shfl_xor_sync(0xffffffffu, l0, 2);
    l1 += __shfl_xor_sync(0xffffffffu, l1, 1);
    l1 += __shfl_xor_sync(0xffffffffu, l1, 2);
    const float inv0 = 1.0f / l0;
    const float inv1 = 1.0f / l1;

    float* op0 = out + (size_t)r0 * NQ + h * HEAD_DIM + 2 * t;
    float* op1 = out + (size_t)r1 * NQ + h * HEAD_DIM + 2 * t;
    #pragma unroll
    for (int d = 0; d < 16; d++) {
        float2 v0 = make_float2(tf32_round(o[d][0] * inv0), tf32_round(o[d][1] * inv0));
        float2 v1 = make_float2(tf32_round(o[d][2] * inv1), tf32_round(o[d][3] * inv1));
        *(float2*)(op0 + d * 8) = v0;
        *(float2*)(op1 + d * 8) = v1;
    }
}

// ---------------------------------------------------------------------------
// Launch
// ---------------------------------------------------------------------------
extern "C" void kernel_launch(void* const* d_in, const int* in_sizes, int n_in,
                              void* d_out, int out_size)
{
    const float* hidden = (const float*)d_in[0];
    const float* cosb   = (const float*)d_in[1];
    const float* sinb   = (const float*)d_in[2];
    const float* w_qkv  = (const float*)d_in[3];
    const float* b_qkv  = (const float*)d_in[4];
    const float* w_o    = (const float*)d_in[5];
    float* out = (float*)d_out;

    float *qkv = nullptr, *attn = nullptr, *Ar = nullptr, *Br = nullptr;
    cudaGetSymbolAddress((void**)&qkv,  g_qkv);
    cudaGetSymbolAddress((void**)&attn, g_attn);
    cudaGetSymbolAddress((void**)&Ar,   g_Ar);
    cudaGetSymbolAddress((void**)&Br,   g_Br);

    cudaFuncSetAttribute(gemm_mma<true>,  cudaFuncAttributeMaxDynamicSharedMemorySize, GSMEM_BYTES);
    cudaFuncSetAttribute(gemm_mma<false>, cudaFuncAttributeMaxDynamicSharedMemorySize, GSMEM_BYTES);
    cudaFuncSetAttribute(flash_tc,        cudaFuncAttributeMaxDynamicSharedMemorySize, FSMEM_BYTES);

    // 0) tf32-round GEMM1 operands
    {
        int n4 = SEQLEN * HIDDEN / 4;
        round_tf32_kernel<<<(n4 + 255) / 256, 256>>>(hidden, Ar, n4);
        n4 = HIDDEN * QKV_OUT / 4;
        round_tf32_kernel<<<(n4 + 255) / 256, 256>>>(w_qkv, Br, n4);
    }

    // 1) QKV projection + bias (tf32 mma.sync)
    gemm_mma<true><<<dim3(QKV_OUT / 128, SEQLEN / 128), 256, GSMEM_BYTES>>>(
        Ar, Br, b_qkv, qkv, HIDDEN, QKV_OUT, QKV_OUT);

    // 2) fused RoPE + tf32-round + dim-major V copy
    {
        int total = SEQLEN * (QKV_OUT / 2);
        rope_round_kernel<<<(total + 255) / 256, 256>>>(cosb, sinb);
    }

    // 3) causal GQA flash attention on tensor cores
    flash_tc<<<dim3(SEQLEN / FBM, NUM_HEADS), 256, FSMEM_BYTES>>>(attn);

    // 4) tf32-round w_o (stream-ordered after GEMM1: safe to reuse Br)
    {
        int n4 = NQ * HIDDEN / 4;
        round_tf32_kernel<<<(n4 + 255) / 256, 256>>>(w_o, Br, n4);
    }

    // 5) output projection (tf32 mma.sync)
    gemm_mma<false><<<dim3(HIDDEN / 128, SEQLEN / 128), 256, GSMEM_BYTES>>>(
        attn, Br, nullptr, out, NQ, HIDDEN, HIDDEN);
}